// round 15
// baseline (speedup 1.0000x reference)
#include <cuda_runtime.h>
#include <cstdint>

// Problem constants (fixed by the reference).
#define BB   4
#define DD   128
#define HH   128
#define WW   128
#define NMAX 500000
#define CIN  32
#define COUT 32
#define KVOL 125
#define GRID_SZ (BB * DD * HH * WW)   // 8,388,608
#define NBUCK (GRID_SZ / 512)         // 16384 buckets of 512 voxels (4 x-rows)
#define EPSV 1e-4f
#define FULLMASK 0xffffffffu
#define SITES_PER_BLOCK 2048          // 8 warps x 256 sites each
#define WSTRIDE 36                    // smem row stride (floats), conflict-free

// -------- device scratch (allocation-free: static __device__ globals) --------
// g_grid holds rank+1 (0 = inactive). Device globals are zero-initialized at
// module load; k_cleanup restores the all-zero state after every run.
__device__ int   g_grid[GRID_SZ];
__device__ int   g_flat[NMAX];             // site (original order) -> flat idx
__device__ int   g_sflat[NMAX];            // rank -> flat idx (bucket-sorted)
__device__ int   g_orig[NMAX];             // rank -> original site row
__device__ int   g_hist[NBUCK];            // bucket histogram / scan bases
__device__ __align__(16) float g_feat[(size_t)NMAX * CIN]; // rank-ordered feats
__device__ __align__(16) float g_acc[(size_t)NMAX * CIN];  // rank-ordered accum
__device__ float g_stats[2 * CIN];

#define CVT_TF32(u, x) asm("cvt.rna.tf32.f32 %0, %1;" : "=r"(u) : "f"(x))
#define MMA_TF32(d, a0, a1, a2, a3, b0, b1)                                    \
    asm volatile("mma.sync.aligned.m16n8k8.row.col.f32.tf32.tf32.f32 "         \
                 "{%0,%1,%2,%3}, {%4,%5,%6,%7}, {%8,%9}, {%0,%1,%2,%3};"       \
                 : "+f"((d)[0]), "+f"((d)[1]), "+f"((d)[2]), "+f"((d)[3])      \
                 : "r"(a0), "r"(a1), "r"(a2), "r"(a3), "r"(b0), "r"(b1))

// -------- launch 0: scatter flat ids + bucket histogram + BN stats ----------
__global__ void k_scatter_stats(const float* __restrict__ x,
                                const int* __restrict__ coords, int Nv) {
    int tid = threadIdx.x;
    int i0 = blockIdx.x * blockDim.x + tid;
    int stride = gridDim.x * blockDim.x;   // multiple of 32

    for (int i = i0; i < Nv; i += stride) {
        int4 c = reinterpret_cast<const int4*>(coords)[i];  // b, z, y, x
        int fl = (((c.x * DD + c.y) * HH + c.z) * WW) + c.w;
        g_flat[i] = fl;
        atomicAdd(&g_hist[fl >> 9], 1);
    }

    __shared__ float ss[8][33];
    __shared__ float ss2[8][33];
    int c = tid & 31;
    int wid = tid >> 5;
    float s = 0.f, s2 = 0.f;
    int total = Nv * CIN;
    for (int e = i0; e < total; e += stride) {
        float v = x[e];
        s += v;
        s2 += v * v;
    }
    ss[wid][c] = s;
    ss2[wid][c] = s2;
    __syncthreads();
    if (tid < 32) {
        float a = 0.f, b = 0.f;
#pragma unroll
        for (int k = 0; k < 8; k++) { a += ss[k][tid]; b += ss2[k][tid]; }
        atomicAdd(&g_stats[tid], a);
        atomicAdd(&g_stats[32 + tid], b);
    }
}

// -------- launch 1: exclusive scan of the bucket histogram ------------------
__global__ void __launch_bounds__(1024) k_scan() {
    __shared__ int part[1024];
    int tid = threadIdx.x;
    int local[16];
    int s = 0;
#pragma unroll
    for (int k = 0; k < 16; k++) { local[k] = s; s += g_hist[tid * 16 + k]; }
    part[tid] = s;
    __syncthreads();
    for (int d = 1; d < 1024; d <<= 1) {
        int v = (tid >= d) ? part[tid - d] : 0;
        __syncthreads();
        part[tid] += v;
        __syncthreads();
    }
    int base = (tid == 0) ? 0 : part[tid - 1];
#pragma unroll
    for (int k = 0; k < 16; k++) g_hist[tid * 16 + k] = base + local[k];
}

// -------- launch 2: assign ranks + grid(rank+1) + normalized rank feats -----
__global__ void __launch_bounds__(256) k_rank_norm(const float* __restrict__ x,
                                                   const float* __restrict__ gamma,
                                                   const float* __restrict__ beta,
                                                   int Nv) {
    __shared__ float sc[32], bi[32];
    __shared__ int rr[256];
    int t = threadIdx.x;
    if (t < 32) {
        float invN = 1.0f / (float)Nv;
        float mean = g_stats[t] * invN;
        float var = g_stats[32 + t] * invN - mean * mean;
        float s = gamma[t] * rsqrtf(var + EPSV);
        sc[t] = s;
        bi[t] = beta[t] - mean * s;
    }
    int i = blockIdx.x * 256 + t;
    if (i < Nv) {
        int fl = g_flat[i];
        int r = atomicAdd(&g_hist[fl >> 9], 1);
        g_sflat[r] = fl;
        g_orig[r] = i;
        g_grid[fl] = r + 1;
        rr[t] = r;
    }
    __syncthreads();
#pragma unroll
    for (int k = 0; k < 8; k++) {
        int e = k * 256 + t;                 // float4 unit within block's span
        int slot = e >> 3, q = e & 7;
        int ii = blockIdx.x * 256 + slot;
        if (ii < Nv) {
            float4 v = __ldg(reinterpret_cast<const float4*>(x) + (size_t)ii * 8 + q);
            int c0 = q * 4;
            float4 o;
            o.x = fmaxf(fmaf(v.x, sc[c0 + 0], bi[c0 + 0]), 0.f);
            o.y = fmaxf(fmaf(v.y, sc[c0 + 1], bi[c0 + 1]), 0.f);
            o.z = fmaxf(fmaf(v.z, sc[c0 + 2], bi[c0 + 2]), 0.f);
            o.w = fmaxf(fmaf(v.w, sc[c0 + 3], bi[c0 + 3]), 0.f);
            reinterpret_cast<float4*>(g_feat)[(size_t)rr[slot] * 8 + q] = o;
        }
    }
}

// -------- launch 3 (PROFILED SLOT): sparse conv via warp MMA ----------------
// Queue compacts valid pairs; batches of 16 pairs run one 16x32x32 GEMM on
// tensor cores (m16n8k8 tf32, 3-term split: fh*wh + fl*wh + fh*wl). Features
// staged into a stride-36 smem tile (bank-conflict-free for both the STS.128
// staging and the per-fragment LDS.32). Weights live as persistent tf32 B
// fragments in registers. Output scatters via red.global.add.v2.f32, guarded
// by the batch fill count.
__global__ void __launch_bounds__(256, 2) k_conv(const float* __restrict__ weight,
                                                 int Nv) {
    const int o = blockIdx.y;
    const int dz = o / 25 - 2;
    const int dy = (o / 5) % 5 - 2;
    const int dx = o % 5 - 2;
    const int doff = dz * (HH * WW) + dy * WW + dx;
    const int lane = threadIdx.x & 31;
    const int wid = threadIdx.x >> 5;

    __shared__ __align__(16) unsigned sA[8][2][16 * WSTRIDE];  // [warp][fh/fl]
    __shared__ int qsm[8][64];                                 // per-warp ring

    // Persistent B fragments: wh/wl pairs for 4x4 (k,n) tiles.
    unsigned wh0[16], wh1[16], wl0[16], wl1[16];
    {
        const float* wp = weight + o * (CIN * COUT);
        const int kk = lane & 3, nn = lane >> 2;
#pragma unroll
        for (int kt = 0; kt < 4; kt++)
#pragma unroll
            for (int nt = 0; nt < 4; nt++) {
                int idx = kt * 4 + nt;
                float w0 = __ldg(wp + (kt * 8 + kk) * COUT + nt * 8 + nn);
                float w1 = __ldg(wp + (kt * 8 + kk + 4) * COUT + nt * 8 + nn);
                unsigned h; float rres;
                CVT_TF32(h, w0); wh0[idx] = h;
                rres = w0 - __uint_as_float(h); CVT_TF32(wl0[idx], rres);
                CVT_TF32(h, w1); wh1[idx] = h;
                rres = w1 - __uint_as_float(h); CVT_TF32(wl1[idx], rres);
            }
    }

    const int warpBase = blockIdx.x * SITES_PER_BLOCK + wid * 256;

    // Preload the 8 rounds' flat ids (coalesced, good MLP).
    int flr[8];
#pragma unroll
    for (int r = 0; r < 8; r++) {
        int s = warpBase + r * 32 + lane;
        flr[r] = __ldg(&g_sflat[s < Nv ? s : (Nv - 1)]);
    }

    int qh = 0, qt = 0;
    const int fr = lane >> 2;        // fragment row group
    const int fc = lane & 3;         // fragment col group

    auto process16 = [&](int rem) {
        __syncwarp(FULLMASK);
        // stage 16 rows as tf32 hi/lo
#pragma unroll
        for (int it = 0; it < 4; it++) {
            int row = it * 4 + (lane >> 3);
            int e = qsm[wid][(qh + row) & 63];
            const float4 f = *reinterpret_cast<const float4*>(
                g_feat + (size_t)(e >> 8) * CIN + (lane & 7) * 4);
            unsigned hx, hy, hz, hw, lx, ly, lz, lw; float t;
            CVT_TF32(hx, f.x); t = f.x - __uint_as_float(hx); CVT_TF32(lx, t);
            CVT_TF32(hy, f.y); t = f.y - __uint_as_float(hy); CVT_TF32(ly, t);
            CVT_TF32(hz, f.z); t = f.z - __uint_as_float(hz); CVT_TF32(lz, t);
            CVT_TF32(hw, f.w); t = f.w - __uint_as_float(hw); CVT_TF32(lw, t);
            int off = row * WSTRIDE + (lane & 7) * 4;
            *reinterpret_cast<uint4*>(&sA[wid][0][off]) = make_uint4(hx, hy, hz, hw);
            *reinterpret_cast<uint4*>(&sA[wid][1][off]) = make_uint4(lx, ly, lz, lw);
        }
        __syncwarp(FULLMASK);

        float D[4][4] = {{0.f, 0.f, 0.f, 0.f}, {0.f, 0.f, 0.f, 0.f},
                         {0.f, 0.f, 0.f, 0.f}, {0.f, 0.f, 0.f, 0.f}};
#pragma unroll
        for (int kt = 0; kt < 4; kt++) {
            int b = fr * WSTRIDE + kt * 8 + fc;
            unsigned a0 = sA[wid][0][b];
            unsigned a1 = sA[wid][0][b + 8 * WSTRIDE];
            unsigned a2 = sA[wid][0][b + 4];
            unsigned a3 = sA[wid][0][b + 8 * WSTRIDE + 4];
            unsigned l0 = sA[wid][1][b];
            unsigned l1 = sA[wid][1][b + 8 * WSTRIDE];
            unsigned l2 = sA[wid][1][b + 4];
            unsigned l3 = sA[wid][1][b + 8 * WSTRIDE + 4];
#pragma unroll
            for (int nt = 0; nt < 4; nt++) {
                int idx = kt * 4 + nt;
                MMA_TF32(D[nt], a0, a1, a2, a3, wh0[idx], wh1[idx]);
                MMA_TF32(D[nt], l0, l1, l2, l3, wh0[idx], wh1[idx]);
                MMA_TF32(D[nt], a0, a1, a2, a3, wl0[idx], wl1[idx]);
            }
        }
        // scatter: lane holds rows fr, fr+8; couts nt*8 + fc*2 + {0,1}
        int eLo = qsm[wid][(qh + fr) & 63];
        int eHi = qsm[wid][(qh + fr + 8) & 63];
        float* pLo = g_acc + (size_t)(warpBase + (eLo & 255)) * COUT + fc * 2;
        float* pHi = g_acc + (size_t)(warpBase + (eHi & 255)) * COUT + fc * 2;
#pragma unroll
        for (int nt = 0; nt < 4; nt++) {
            if (fr < rem)
                asm volatile("red.global.add.v2.f32 [%0], {%1,%2};"
                             :: "l"(pLo + nt * 8), "f"(D[nt][0]), "f"(D[nt][1]));
            if (fr + 8 < rem)
                asm volatile("red.global.add.v2.f32 [%0], {%1,%2};"
                             :: "l"(pHi + nt * 8), "f"(D[nt][2]), "f"(D[nt][3]));
        }
    };

#pragma unroll 1
    for (int r = 0; r < 8; r++) {
        int s = warpBase + r * 32 + lane;
        int fl = flr[r];
        int nidx = -1;
        if (s < Nv) {
            int z = (fl >> 14) & 127, y = (fl >> 7) & 127, x = fl & 127;
            if (((unsigned)(z + dz) < 128u) & ((unsigned)(y + dy) < 128u) &
                ((unsigned)(x + dx) < 128u)) {
                nidx = __ldg(&g_grid[fl + doff]) - 1;   // rank or -1
            }
        }
        unsigned mask = __ballot_sync(FULLMASK, nidx >= 0);
        if (nidx >= 0) {
            int pos = qt + __popc(mask & ((1u << lane) - 1u));
            qsm[wid][pos & 63] = (nidx << 8) | (r * 32 + lane);
        }
        qt += __popc(mask);
        __syncwarp(FULLMASK);
        while (qt - qh >= 16) { process16(16); qh += 16; }
    }
    int rem = qt - qh;
    if (rem > 0) {
        int e0 = qsm[wid][qh & 63];
        if (lane < 16 - rem) qsm[wid][(qt + lane) & 63] = e0;  // pad
        __syncwarp(FULLMASK);
        process16(rem);
    }
}

// -------- launch 4: permute accumulator back to original row order ----------
__global__ void k_permute(float* __restrict__ out, int Nv) {
    int e = blockIdx.x * blockDim.x + threadIdx.x;  // float4 units
    int total = Nv * (CIN / 4);
    if (e < total) {
        int r = e >> 3, q = e & 7;
        float4 v = reinterpret_cast<const float4*>(g_acc)[e];
        reinterpret_cast<float4*>(out)[(size_t)__ldg(&g_orig[r]) * 8 + q] = v;
    }
}

// -------- launch 5: restore all-zero scratch state --------------------------
__global__ void k_cleanup(int Nv) {
    int i = blockIdx.x * blockDim.x + threadIdx.x;
    int stride = gridDim.x * blockDim.x;
    for (int e = i; e < Nv; e += stride) g_grid[g_flat[e]] = 0;
    for (int e = i; e < NBUCK; e += stride) g_hist[e] = 0;
    if (i < 2 * CIN) g_stats[i] = 0.f;
    float4 z4 = make_float4(0.f, 0.f, 0.f, 0.f);
    int total4 = Nv * (CIN / 4);
    for (int e = i; e < total4; e += stride)
        reinterpret_cast<float4*>(g_acc)[e] = z4;
}

// -------- launch ------------------------------------------------------------
extern "C" void kernel_launch(void* const* d_in, const int* in_sizes, int n_in,
                              void* d_out, int out_size) {
    const float* feats  = (const float*)d_in[0];   // [N, 32]
    const int*   coords = (const int*)d_in[1];     // [N, 4]
    const float* gamma  = (const float*)d_in[2];   // [32]
    const float* beta   = (const float*)d_in[3];   // [32]
    const float* weight = (const float*)d_in[4];   // [125, 32, 32]
    float* out = (float*)d_out;                    // [N, 32]

    int Nv = in_sizes[0] / CIN;
    if (Nv > NMAX) Nv = NMAX;

    k_scatter_stats<<<1024, 256>>>(feats, coords, Nv);               // 0
    k_scan<<<1, 1024>>>();                                           // 1
    k_rank_norm<<<(Nv + 255) / 256, 256>>>(feats, gamma, beta, Nv);  // 2
    dim3 gc((Nv + SITES_PER_BLOCK - 1) / SITES_PER_BLOCK, KVOL);
    k_conv<<<gc, 256>>>(weight, Nv);                                 // 3 (profiled)
    k_permute<<<(Nv * (CIN / 4) + 255) / 256, 256>>>(out, Nv);       // 4
    k_cleanup<<<2048, 256>>>(Nv);                                    // 5
}

// round 16
// speedup vs baseline: 1.0728x; 1.0728x over previous
#include <cuda_runtime.h>
#include <cstdint>

// Problem constants (fixed by the reference).
#define BB   4
#define DD   128
#define HH   128
#define WW   128
#define NMAX 500000
#define CIN  32
#define COUT 32
#define KVOL 125
#define GRID_SZ (BB * DD * HH * WW)   // 8,388,608
#define NBUCK (GRID_SZ / 512)         // 16384 buckets of 512 voxels (4 x-rows)
#define EPSV 1e-4f
#define FULLMASK 0xffffffffu
#define SITES_PER_BLOCK 2048          // 8 warps x 256 sites each
#define TSTRIDE 36                    // padded smem row stride (floats)

// -------- device scratch (allocation-free: static __device__ globals) --------
// g_grid holds rank+1 (0 = inactive). Device globals are zero-initialized at
// module load; k_cleanup restores the all-zero state after every run.
__device__ int   g_grid[GRID_SZ];
__device__ int   g_flat[NMAX];             // site (original order) -> flat idx
__device__ int   g_sflat[NMAX];            // rank -> flat idx (bucket-sorted)
__device__ int   g_orig[NMAX];             // rank -> original site row
__device__ int   g_hist[NBUCK];            // bucket histogram / scan bases
__device__ __align__(16) float g_feat[(size_t)NMAX * CIN]; // rank-ordered feats
__device__ __align__(16) float g_acc[(size_t)NMAX * CIN];  // rank-ordered accum
__device__ float g_stats[2 * CIN];

// f32x2 packed FMA — PTX only.
#define FFMA2(acc, f2, w2) \
    asm("fma.rn.f32x2 %0, %1, %2, %3;" : "=l"(acc) : "l"(f2), "l"(w2), "l"(acc))

// -------- launch 0: scatter flat ids + bucket histogram + BN stats ----------
__global__ void k_scatter_stats(const float* __restrict__ x,
                                const int* __restrict__ coords, int Nv) {
    int tid = threadIdx.x;
    int i0 = blockIdx.x * blockDim.x + tid;
    int stride = gridDim.x * blockDim.x;   // multiple of 32

    for (int i = i0; i < Nv; i += stride) {
        int4 c = reinterpret_cast<const int4*>(coords)[i];  // b, z, y, x
        int fl = (((c.x * DD + c.y) * HH + c.z) * WW) + c.w;
        g_flat[i] = fl;
        atomicAdd(&g_hist[fl >> 9], 1);
    }

    __shared__ float ss[8][33];
    __shared__ float ss2[8][33];
    int c = tid & 31;
    int wid = tid >> 5;
    float s = 0.f, s2 = 0.f;
    int total = Nv * CIN;
    for (int e = i0; e < total; e += stride) {
        float v = x[e];
        s += v;
        s2 += v * v;
    }
    ss[wid][c] = s;
    ss2[wid][c] = s2;
    __syncthreads();
    if (tid < 32) {
        float a = 0.f, b = 0.f;
#pragma unroll
        for (int k = 0; k < 8; k++) { a += ss[k][tid]; b += ss2[k][tid]; }
        atomicAdd(&g_stats[tid], a);
        atomicAdd(&g_stats[32 + tid], b);
    }
}

// -------- launch 1: exclusive scan of the bucket histogram ------------------
__global__ void __launch_bounds__(1024) k_scan() {
    __shared__ int part[1024];
    int tid = threadIdx.x;
    int local[16];
    int s = 0;
#pragma unroll
    for (int k = 0; k < 16; k++) { local[k] = s; s += g_hist[tid * 16 + k]; }
    part[tid] = s;
    __syncthreads();
    for (int d = 1; d < 1024; d <<= 1) {
        int v = (tid >= d) ? part[tid - d] : 0;
        __syncthreads();
        part[tid] += v;
        __syncthreads();
    }
    int base = (tid == 0) ? 0 : part[tid - 1];
#pragma unroll
    for (int k = 0; k < 16; k++) g_hist[tid * 16 + k] = base + local[k];
}

// -------- launch 2: assign ranks + grid(rank+1) + normalized rank feats -----
__global__ void __launch_bounds__(256) k_rank_norm(const float* __restrict__ x,
                                                   const float* __restrict__ gamma,
                                                   const float* __restrict__ beta,
                                                   int Nv) {
    __shared__ float sc[32], bi[32];
    __shared__ int rr[256];
    int t = threadIdx.x;
    if (t < 32) {
        float invN = 1.0f / (float)Nv;
        float mean = g_stats[t] * invN;
        float var = g_stats[32 + t] * invN - mean * mean;
        float s = gamma[t] * rsqrtf(var + EPSV);
        sc[t] = s;
        bi[t] = beta[t] - mean * s;
    }
    int i = blockIdx.x * 256 + t;
    if (i < Nv) {
        int fl = g_flat[i];
        int r = atomicAdd(&g_hist[fl >> 9], 1);
        g_sflat[r] = fl;
        g_orig[r] = i;
        g_grid[fl] = r + 1;
        rr[t] = r;
    }
    __syncthreads();
#pragma unroll
    for (int k = 0; k < 8; k++) {
        int e = k * 256 + t;                 // float4 unit within block's span
        int slot = e >> 3, q = e & 7;
        int ii = blockIdx.x * 256 + slot;
        if (ii < Nv) {
            float4 v = __ldg(reinterpret_cast<const float4*>(x) + (size_t)ii * 8 + q);
            int c0 = q * 4;
            float4 o;
            o.x = fmaxf(fmaf(v.x, sc[c0 + 0], bi[c0 + 0]), 0.f);
            o.y = fmaxf(fmaf(v.y, sc[c0 + 1], bi[c0 + 1]), 0.f);
            o.z = fmaxf(fmaf(v.z, sc[c0 + 2], bi[c0 + 2]), 0.f);
            o.w = fmaxf(fmaf(v.w, sc[c0 + 3], bi[c0 + 3]), 0.f);
            reinterpret_cast<float4*>(g_feat)[(size_t)rr[slot] * 8 + q] = o;
        }
    }
}

// -------- launch 3 (PROFILED SLOT): sparse conv, one offset per blockIdx.y --
// Per warp: compact valid pairs from 32-site ballot rounds into a smem ring,
// drain in batches of 8. Each batch stages its 8 feature rows coalesced into
// smem, computes two groups of 4 packed-FMA GEMV chains from uniform LDS
// broadcasts, transposes through a padded (stride-36, conflict-free) tile, and
// scatters 8 couts per lane via two red.global.add.v4.f32.
__global__ void __launch_bounds__(256, 4) k_conv(const float* __restrict__ weight,
                                                 int Nv) {
    const int o = blockIdx.y;
    const int dz = o / 25 - 2;
    const int dy = (o / 5) % 5 - 2;
    const int dx = o % 5 - 2;
    const int doff = dz * (HH * WW) + dy * WW + dx;
    const int lane = threadIdx.x & 31;
    const int wid = threadIdx.x >> 5;

    __shared__ __align__(16) float ftile[8][8][TSTRIDE];  // staged rows  (~9KB)
    __shared__ __align__(16) float ttile[8][8][TSTRIDE];  // transpose    (~9KB)
    __shared__ int qsm[8][64];                            // per-warp ring (2KB)

    // Packed weight column: w2[t] = (W[2t][lane], W[2t+1][lane]); once / block.
    unsigned long long w2[16];
    {
        const float* wp = weight + o * (CIN * COUT) + lane;
#pragma unroll
        for (int t = 0; t < 16; t++) {
            float a = __ldg(wp + (2 * t) * COUT);
            float b = __ldg(wp + (2 * t + 1) * COUT);
            asm("mov.b64 %0, {%1, %2};" : "=l"(w2[t]) : "f"(a), "f"(b));
        }
    }

    const int warpBase = blockIdx.x * SITES_PER_BLOCK + wid * 256;
    const int p  = lane >> 2;        // which of the 8 batched pairs this lane stores
    const int c8 = (lane & 3) * 8;   // cout base (8 couts per lane)

    int qh = 0, qt = 0;

    // One group of 4 GEMV chains over staged rows [g*4 .. g*4+3].
    auto compute4 = [&](int g) {
        const float* r0p = ftile[wid][g * 4 + 0];
        const float* r1p = ftile[wid][g * 4 + 1];
        const float* r2p = ftile[wid][g * 4 + 2];
        const float* r3p = ftile[wid][g * 4 + 3];
        unsigned long long a0 = 0ull, a1 = 0ull, a2 = 0ull, a3 = 0ull;
#pragma unroll
        for (int k = 0; k < 8; k++) {
            ulonglong2 q0 = *reinterpret_cast<const ulonglong2*>(r0p + k * 4);
            ulonglong2 q1 = *reinterpret_cast<const ulonglong2*>(r1p + k * 4);
            ulonglong2 q2 = *reinterpret_cast<const ulonglong2*>(r2p + k * 4);
            ulonglong2 q3 = *reinterpret_cast<const ulonglong2*>(r3p + k * 4);
            FFMA2(a0, q0.x, w2[2 * k]); FFMA2(a0, q0.y, w2[2 * k + 1]);
            FFMA2(a1, q1.x, w2[2 * k]); FFMA2(a1, q1.y, w2[2 * k + 1]);
            FFMA2(a2, q2.x, w2[2 * k]); FFMA2(a2, q2.y, w2[2 * k + 1]);
            FFMA2(a3, q3.x, w2[2 * k]); FFMA2(a3, q3.y, w2[2 * k + 1]);
        }
        float lo, hi;
        asm("mov.b64 {%0, %1}, %2;" : "=f"(lo), "=f"(hi) : "l"(a0));
        ttile[wid][g * 4 + 0][lane] = lo + hi;
        asm("mov.b64 {%0, %1}, %2;" : "=f"(lo), "=f"(hi) : "l"(a1));
        ttile[wid][g * 4 + 1][lane] = lo + hi;
        asm("mov.b64 {%0, %1}, %2;" : "=f"(lo), "=f"(hi) : "l"(a2));
        ttile[wid][g * 4 + 2][lane] = lo + hi;
        asm("mov.b64 {%0, %1}, %2;" : "=f"(lo), "=f"(hi) : "l"(a3));
        ttile[wid][g * 4 + 3][lane] = lo + hi;
    };

    auto process8 = [&](int rem) {
        __syncwarp(FULLMASK);   // prior batch's tile reads complete; pads visible
        // stage 8 rows, coalesced: 8 lanes per row, float4 each
#pragma unroll
        for (int it = 0; it < 2; it++) {
            int row = it * 4 + (lane >> 3);
            int e = qsm[wid][(qh + row) & 63];
            float4 f = *reinterpret_cast<const float4*>(
                g_feat + (size_t)(e >> 8) * CIN + (lane & 7) * 4);
            *reinterpret_cast<float4*>(&ftile[wid][row][(lane & 7) * 4]) = f;
        }
        __syncwarp(FULLMASK);
        compute4(0);
        compute4(1);
        __syncwarp(FULLMASK);
        int ep = qsm[wid][(qh + p) & 63];
        float4 v0 = *reinterpret_cast<const float4*>(&ttile[wid][p][c8]);
        float4 v1 = *reinterpret_cast<const float4*>(&ttile[wid][p][c8 + 4]);
        if (p < rem) {
            float* dst = g_acc + (size_t)(warpBase + (ep & 255)) * COUT + c8;
            asm volatile("red.global.add.v4.f32 [%0], {%1, %2, %3, %4};"
                         :: "l"(dst), "f"(v0.x), "f"(v0.y), "f"(v0.z), "f"(v0.w));
            asm volatile("red.global.add.v4.f32 [%0], {%1, %2, %3, %4};"
                         :: "l"(dst + 4), "f"(v1.x), "f"(v1.y), "f"(v1.z), "f"(v1.w));
        }
    };

    // 1-deep sflat prefetch (2 regs instead of an 8-reg preload).
    int s0 = warpBase + lane;
    int fl_next = __ldg(&g_sflat[s0 < Nv ? s0 : (Nv - 1)]);

#pragma unroll 1
    for (int r = 0; r < 8; r++) {
        int fl = fl_next;
        if (r < 7) {
            int sn = warpBase + (r + 1) * 32 + lane;
            fl_next = __ldg(&g_sflat[sn < Nv ? sn : (Nv - 1)]);
        }
        int s = warpBase + r * 32 + lane;
        int nidx = -1;
        if (s < Nv) {
            int z = (fl >> 14) & 127, y = (fl >> 7) & 127, x = fl & 127;
            if (((unsigned)(z + dz) < 128u) & ((unsigned)(y + dy) < 128u) &
                ((unsigned)(x + dx) < 128u)) {
                nidx = __ldg(&g_grid[fl + doff]) - 1;   // rank or -1
            }
        }
        unsigned mask = __ballot_sync(FULLMASK, nidx >= 0);
        if (nidx >= 0) {
            int pos = qt + __popc(mask & ((1u << lane) - 1u));
            qsm[wid][pos & 63] = (nidx << 8) | (r * 32 + lane);   // nidx<19b, loc<8b
        }
        qt += __popc(mask);
        __syncwarp(FULLMASK);
        while (qt - qh >= 8) { process8(8); qh += 8; }
    }
    int rem = qt - qh;
    if (rem > 0) {
        int e0 = qsm[wid][qh & 63];
        if (lane < 8 - rem) qsm[wid][(qt + lane) & 63] = e0;  // pad to 8
        process8(rem);   // leading syncwarp makes pads visible
    }
}

// -------- launch 4: permute accumulator back to original row order ----------
__global__ void k_permute(float* __restrict__ out, int Nv) {
    int e = blockIdx.x * blockDim.x + threadIdx.x;  // float4 units
    int total = Nv * (CIN / 4);
    if (e < total) {
        int r = e >> 3, q = e & 7;
        float4 v = reinterpret_cast<const float4*>(g_acc)[e];
        reinterpret_cast<float4*>(out)[(size_t)__ldg(&g_orig[r]) * 8 + q] = v;
    }
}

// -------- launch 5: restore all-zero scratch state --------------------------
__global__ void k_cleanup(int Nv) {
    int i = blockIdx.x * blockDim.x + threadIdx.x;
    int stride = gridDim.x * blockDim.x;
    for (int e = i; e < Nv; e += stride) g_grid[g_flat[e]] = 0;
    for (int e = i; e < NBUCK; e += stride) g_hist[e] = 0;
    if (i < 2 * CIN) g_stats[i] = 0.f;
    float4 z4 = make_float4(0.f, 0.f, 0.f, 0.f);
    int total4 = Nv * (CIN / 4);
    for (int e = i; e < total4; e += stride)
        reinterpret_cast<float4*>(g_acc)[e] = z4;
}

// -------- launch ------------------------------------------------------------
extern "C" void kernel_launch(void* const* d_in, const int* in_sizes, int n_in,
                              void* d_out, int out_size) {
    const float* feats  = (const float*)d_in[0];   // [N, 32]
    const int*   coords = (const int*)d_in[1];     // [N, 4]
    const float* gamma  = (const float*)d_in[2];   // [32]
    const float* beta   = (const float*)d_in[3];   // [32]
    const float* weight = (const float*)d_in[4];   // [125, 32, 32]
    float* out = (float*)d_out;                    // [N, 32]

    int Nv = in_sizes[0] / CIN;
    if (Nv > NMAX) Nv = NMAX;

    k_scatter_stats<<<1024, 256>>>(feats, coords, Nv);               // 0
    k_scan<<<1, 1024>>>();                                           // 1
    k_rank_norm<<<(Nv + 255) / 256, 256>>>(feats, gamma, beta, Nv);  // 2
    dim3 gc((Nv + SITES_PER_BLOCK - 1) / SITES_PER_BLOCK, KVOL);
    k_conv<<<gc, 256>>>(weight, Nv);                                 // 3 (profiled)
    k_permute<<<(Nv * (CIN / 4) + 255) / 256, 256>>>(out, Nv);       // 4
    k_cleanup<<<2048, 256>>>(Nv);                                    // 5
}

// round 17
// speedup vs baseline: 1.5690x; 1.4624x over previous
#include <cuda_runtime.h>
#include <cstdint>

// Problem constants (fixed by the reference).
#define BB   4
#define DD   128
#define HH   128
#define WW   128
#define NMAX 500000
#define CIN  32
#define COUT 32
#define KVOL 125
#define GRID_SZ (BB * DD * HH * WW)   // 8,388,608
#define NBUCK (GRID_SZ / 512)         // 16384 buckets of 512 voxels (4 x-rows)
#define EPSV 1e-4f
#define FULLMASK 0xffffffffu
#define SITES_PER_BLOCK 2048          // 8 warps x 256 sites each
#define WSTRIDE 36                    // smem A-tile row stride (uints)

// -------- device scratch (allocation-free: static __device__ globals) --------
// g_grid holds rank+1 (0 = inactive). Device globals are zero-initialized at
// module load; k_cleanup restores the all-zero state after every run.
__device__ int   g_grid[GRID_SZ];
__device__ int   g_flat[NMAX];             // site (original order) -> flat idx
__device__ int   g_sflat[NMAX];            // rank -> flat idx (bucket-sorted)
__device__ int   g_orig[NMAX];             // rank -> original site row
__device__ int   g_hist[NBUCK];            // bucket histogram / scan bases
__device__ __align__(16) float g_feat[(size_t)NMAX * CIN]; // rank-ordered feats
__device__ __align__(16) float g_acc[(size_t)NMAX * CIN];  // rank-ordered accum
__device__ float g_stats[2 * CIN];

#define CVT_TF32(u, x) asm("cvt.rna.tf32.f32 %0, %1;" : "=r"(u) : "f"(x))
#define MMA_TF32(d, a0, a1, a2, a3, b0, b1)                                    \
    asm volatile("mma.sync.aligned.m16n8k8.row.col.f32.tf32.tf32.f32 "         \
                 "{%0,%1,%2,%3}, {%4,%5,%6,%7}, {%8,%9}, {%0,%1,%2,%3};"       \
                 : "+f"((d)[0]), "+f"((d)[1]), "+f"((d)[2]), "+f"((d)[3])      \
                 : "r"(a0), "r"(a1), "r"(a2), "r"(a3), "r"(b0), "r"(b1))

// -------- launch 0: scatter flat ids + bucket histogram + BN stats ----------
__global__ void k_scatter_stats(const float* __restrict__ x,
                                const int* __restrict__ coords, int Nv) {
    int tid = threadIdx.x;
    int i0 = blockIdx.x * blockDim.x + tid;
    int stride = gridDim.x * blockDim.x;   // multiple of 32

    for (int i = i0; i < Nv; i += stride) {
        int4 c = reinterpret_cast<const int4*>(coords)[i];  // b, z, y, x
        int fl = (((c.x * DD + c.y) * HH + c.z) * WW) + c.w;
        g_flat[i] = fl;
        atomicAdd(&g_hist[fl >> 9], 1);
    }

    __shared__ float ss[8][33];
    __shared__ float ss2[8][33];
    int c = tid & 31;
    int wid = tid >> 5;
    float s = 0.f, s2 = 0.f;
    int total = Nv * CIN;
    for (int e = i0; e < total; e += stride) {
        float v = x[e];
        s += v;
        s2 += v * v;
    }
    ss[wid][c] = s;
    ss2[wid][c] = s2;
    __syncthreads();
    if (tid < 32) {
        float a = 0.f, b = 0.f;
#pragma unroll
        for (int k = 0; k < 8; k++) { a += ss[k][tid]; b += ss2[k][tid]; }
        atomicAdd(&g_stats[tid], a);
        atomicAdd(&g_stats[32 + tid], b);
    }
}

// -------- launch 1: exclusive scan of the bucket histogram ------------------
__global__ void __launch_bounds__(1024) k_scan() {
    __shared__ int part[1024];
    int tid = threadIdx.x;
    int local[16];
    int s = 0;
#pragma unroll
    for (int k = 0; k < 16; k++) { local[k] = s; s += g_hist[tid * 16 + k]; }
    part[tid] = s;
    __syncthreads();
    for (int d = 1; d < 1024; d <<= 1) {
        int v = (tid >= d) ? part[tid - d] : 0;
        __syncthreads();
        part[tid] += v;
        __syncthreads();
    }
    int base = (tid == 0) ? 0 : part[tid - 1];
#pragma unroll
    for (int k = 0; k < 16; k++) g_hist[tid * 16 + k] = base + local[k];
}

// -------- launch 2: assign ranks + grid(rank+1) + normalized rank feats -----
__global__ void __launch_bounds__(256) k_rank_norm(const float* __restrict__ x,
                                                   const float* __restrict__ gamma,
                                                   const float* __restrict__ beta,
                                                   int Nv) {
    __shared__ float sc[32], bi[32];
    __shared__ int rr[256];
    int t = threadIdx.x;
    if (t < 32) {
        float invN = 1.0f / (float)Nv;
        float mean = g_stats[t] * invN;
        float var = g_stats[32 + t] * invN - mean * mean;
        float s = gamma[t] * rsqrtf(var + EPSV);
        sc[t] = s;
        bi[t] = beta[t] - mean * s;
    }
    int i = blockIdx.x * 256 + t;
    if (i < Nv) {
        int fl = g_flat[i];
        int r = atomicAdd(&g_hist[fl >> 9], 1);
        g_sflat[r] = fl;
        g_orig[r] = i;
        g_grid[fl] = r + 1;
        rr[t] = r;
    }
    __syncthreads();
#pragma unroll
    for (int k = 0; k < 8; k++) {
        int e = k * 256 + t;                 // float4 unit within block's span
        int slot = e >> 3, q = e & 7;
        int ii = blockIdx.x * 256 + slot;
        if (ii < Nv) {
            float4 v = __ldg(reinterpret_cast<const float4*>(x) + (size_t)ii * 8 + q);
            int c0 = q * 4;
            float4 o;
            o.x = fmaxf(fmaf(v.x, sc[c0 + 0], bi[c0 + 0]), 0.f);
            o.y = fmaxf(fmaf(v.y, sc[c0 + 1], bi[c0 + 1]), 0.f);
            o.z = fmaxf(fmaf(v.z, sc[c0 + 2], bi[c0 + 2]), 0.f);
            o.w = fmaxf(fmaf(v.w, sc[c0 + 3], bi[c0 + 3]), 0.f);
            reinterpret_cast<float4*>(g_feat)[(size_t)rr[slot] * 8 + q] = o;
        }
    }
}

// -------- launch 3 (PROFILED SLOT): sparse conv via warp MMA ----------------
// Same engine as the correctness-validated R15 kernel (m16n8k8 tf32, 3-term
// split fh*wh + fl*wh + fh*wl over 16-pair batches), with ONE change: the
// per-offset B fragments live in SMEM (staged once per block) instead of 64
// persistent registers. Register count drops ~112 -> ~56, restoring 4 CTAs/SM.
__global__ void __launch_bounds__(256, 4) k_conv(const float* __restrict__ weight,
                                                 int Nv) {
    const int o = blockIdx.y;
    const int dz = o / 25 - 2;
    const int dy = (o / 5) % 5 - 2;
    const int dx = o % 5 - 2;
    const int doff = dz * (HH * WW) + dy * WW + dx;
    const int lane = threadIdx.x & 31;
    const int wid = threadIdx.x >> 5;

    __shared__ __align__(16) unsigned sA[8][2][16 * WSTRIDE];  // [warp][fh/fl] ~37KB
    __shared__ __align__(8) uint2 sWh[16][32];                 // B frags hi (4KB)
    __shared__ __align__(8) uint2 sWl[16][32];                 // B frags lo (4KB)
    __shared__ int qsm[8][64];                                 // per-warp ring (2KB)

    // Stage all B fragments for this offset into smem (once per block).
    // Fragment layout (validated in R15): for tile idx = kt*4+nt, lane with
    // kk=lane&3, nn=lane>>2 holds {W[kt*8+kk][nt*8+nn], W[kt*8+kk+4][nt*8+nn]}.
    {
        const float* wp = weight + o * (CIN * COUT);
        for (int e = threadIdx.x; e < 512; e += 256) {
            int tile = e >> 5, ln = e & 31;
            int kt = tile >> 2, nt = tile & 3;
            int kk = ln & 3, nn = ln >> 2;
            float w0 = __ldg(wp + (kt * 8 + kk) * COUT + nt * 8 + nn);
            float w1 = __ldg(wp + (kt * 8 + kk + 4) * COUT + nt * 8 + nn);
            unsigned h0, h1, l0, l1; float t;
            CVT_TF32(h0, w0); t = w0 - __uint_as_float(h0); CVT_TF32(l0, t);
            CVT_TF32(h1, w1); t = w1 - __uint_as_float(h1); CVT_TF32(l1, t);
            sWh[tile][ln] = make_uint2(h0, h1);
            sWl[tile][ln] = make_uint2(l0, l1);
        }
    }
    __syncthreads();

    const int warpBase = blockIdx.x * SITES_PER_BLOCK + wid * 256;

    // Preload the 8 rounds' flat ids (coalesced, good MLP).
    int flr[8];
#pragma unroll
    for (int r = 0; r < 8; r++) {
        int s = warpBase + r * 32 + lane;
        flr[r] = __ldg(&g_sflat[s < Nv ? s : (Nv - 1)]);
    }

    int qh = 0, qt = 0;
    const int fr = lane >> 2;        // fragment row group
    const int fc = lane & 3;         // fragment col group

    auto process16 = [&](int rem) {
        __syncwarp(FULLMASK);
        // stage 16 rows as tf32 hi/lo
#pragma unroll
        for (int it = 0; it < 4; it++) {
            int row = it * 4 + (lane >> 3);
            int e = qsm[wid][(qh + row) & 63];
            const float4 f = *reinterpret_cast<const float4*>(
                g_feat + (size_t)(e >> 8) * CIN + (lane & 7) * 4);
            unsigned hx, hy, hz, hw, lx, ly, lz, lw; float t;
            CVT_TF32(hx, f.x); t = f.x - __uint_as_float(hx); CVT_TF32(lx, t);
            CVT_TF32(hy, f.y); t = f.y - __uint_as_float(hy); CVT_TF32(ly, t);
            CVT_TF32(hz, f.z); t = f.z - __uint_as_float(hz); CVT_TF32(lz, t);
            CVT_TF32(hw, f.w); t = f.w - __uint_as_float(hw); CVT_TF32(lw, t);
            int off = row * WSTRIDE + (lane & 7) * 4;
            *reinterpret_cast<uint4*>(&sA[wid][0][off]) = make_uint4(hx, hy, hz, hw);
            *reinterpret_cast<uint4*>(&sA[wid][1][off]) = make_uint4(lx, ly, lz, lw);
        }
        __syncwarp(FULLMASK);

        float D[4][4] = {{0.f, 0.f, 0.f, 0.f}, {0.f, 0.f, 0.f, 0.f},
                         {0.f, 0.f, 0.f, 0.f}, {0.f, 0.f, 0.f, 0.f}};
#pragma unroll
        for (int kt = 0; kt < 4; kt++) {
            int b = fr * WSTRIDE + kt * 8 + fc;
            unsigned a0 = sA[wid][0][b];
            unsigned a1 = sA[wid][0][b + 8 * WSTRIDE];
            unsigned a2 = sA[wid][0][b + 4];
            unsigned a3 = sA[wid][0][b + 8 * WSTRIDE + 4];
            unsigned l0 = sA[wid][1][b];
            unsigned l1 = sA[wid][1][b + 8 * WSTRIDE];
            unsigned l2 = sA[wid][1][b + 4];
            unsigned l3 = sA[wid][1][b + 8 * WSTRIDE + 4];
#pragma unroll
            for (int nt = 0; nt < 4; nt++) {
                int idx = kt * 4 + nt;
                uint2 bh = sWh[idx][lane];
                uint2 bl = sWl[idx][lane];
                MMA_TF32(D[nt], a0, a1, a2, a3, bh.x, bh.y);
                MMA_TF32(D[nt], l0, l1, l2, l3, bh.x, bh.y);
                MMA_TF32(D[nt], a0, a1, a2, a3, bl.x, bl.y);
            }
        }
        // scatter: lane holds rows fr, fr+8; couts nt*8 + fc*2 + {0,1}
        int eLo = qsm[wid][(qh + fr) & 63];
        int eHi = qsm[wid][(qh + fr + 8) & 63];
        float* pLo = g_acc + (size_t)(warpBase + (eLo & 255)) * COUT + fc * 2;
        float* pHi = g_acc + (size_t)(warpBase + (eHi & 255)) * COUT + fc * 2;
#pragma unroll
        for (int nt = 0; nt < 4; nt++) {
            if (fr < rem)
                asm volatile("red.global.add.v2.f32 [%0], {%1,%2};"
                             :: "l"(pLo + nt * 8), "f"(D[nt][0]), "f"(D[nt][1]));
            if (fr + 8 < rem)
                asm volatile("red.global.add.v2.f32 [%0], {%1,%2};"
                             :: "l"(pHi + nt * 8), "f"(D[nt][2]), "f"(D[nt][3]));
        }
    };

#pragma unroll 1
    for (int r = 0; r < 8; r++) {
        int s = warpBase + r * 32 + lane;
        int fl = flr[r];
        int nidx = -1;
        if (s < Nv) {
            int z = (fl >> 14) & 127, y = (fl >> 7) & 127, x = fl & 127;
            if (((unsigned)(z + dz) < 128u) & ((unsigned)(y + dy) < 128u) &
                ((unsigned)(x + dx) < 128u)) {
                nidx = __ldg(&g_grid[fl + doff]) - 1;   // rank or -1
            }
        }
        unsigned mask = __ballot_sync(FULLMASK, nidx >= 0);
        if (nidx >= 0) {
            int pos = qt + __popc(mask & ((1u << lane) - 1u));
            qsm[wid][pos & 63] = (nidx << 8) | (r * 32 + lane);
        }
        qt += __popc(mask);
        __syncwarp(FULLMASK);
        while (qt - qh >= 16) { process16(16); qh += 16; }
    }
    int rem = qt - qh;
    if (rem > 0) {
        int e0 = qsm[wid][qh & 63];
        if (lane < 16 - rem) qsm[wid][(qt + lane) & 63] = e0;  // pad
        __syncwarp(FULLMASK);
        process16(rem);
    }
}

// -------- launch 4: permute accumulator back to original row order ----------
__global__ void k_permute(float* __restrict__ out, int Nv) {
    int e = blockIdx.x * blockDim.x + threadIdx.x;  // float4 units
    int total = Nv * (CIN / 4);
    if (e < total) {
        int r = e >> 3, q = e & 7;
        float4 v = reinterpret_cast<const float4*>(g_acc)[e];
        reinterpret_cast<float4*>(out)[(size_t)__ldg(&g_orig[r]) * 8 + q] = v;
    }
}

// -------- launch 5: restore all-zero scratch state --------------------------
__global__ void k_cleanup(int Nv) {
    int i = blockIdx.x * blockDim.x + threadIdx.x;
    int stride = gridDim.x * blockDim.x;
    for (int e = i; e < Nv; e += stride) g_grid[g_flat[e]] = 0;
    for (int e = i; e < NBUCK; e += stride) g_hist[e] = 0;
    if (i < 2 * CIN) g_stats[i] = 0.f;
    float4 z4 = make_float4(0.f, 0.f, 0.f, 0.f);
    int total4 = Nv * (CIN / 4);
    for (int e = i; e < total4; e += stride)
        reinterpret_cast<float4*>(g_acc)[e] = z4;
}

// -------- launch ------------------------------------------------------------
extern "C" void kernel_launch(void* const* d_in, const int* in_sizes, int n_in,
                              void* d_out, int out_size) {
    const float* feats  = (const float*)d_in[0];   // [N, 32]
    const int*   coords = (const int*)d_in[1];     // [N, 4]
    const float* gamma  = (const float*)d_in[2];   // [32]
    const float* beta   = (const float*)d_in[3];   // [32]
    const float* weight = (const float*)d_in[4];   // [125, 32, 32]
    float* out = (float*)d_out;                    // [N, 32]

    int Nv = in_sizes[0] / CIN;
    if (Nv > NMAX) Nv = NMAX;

    k_scatter_stats<<<1024, 256>>>(feats, coords, Nv);               // 0
    k_scan<<<1, 1024>>>();                                           // 1
    k_rank_norm<<<(Nv + 255) / 256, 256>>>(feats, gamma, beta, Nv);  // 2
    dim3 gc((Nv + SITES_PER_BLOCK - 1) / SITES_PER_BLOCK, KVOL);
    k_conv<<<gc, 256>>>(weight, Nv);                                 // 3 (profiled)
    k_permute<<<(Nv * (CIN / 4) + 255) / 256, 256>>>(out, Nv);       // 4
    k_cleanup<<<2048, 256>>>(Nv);                                    // 5
}